// round 3
// baseline (speedup 1.0000x reference)
#include <cuda_runtime.h>
#include <cuda_bf16.h>
#include <cstdint>

// Problem: 2-layer GCN on 100k nodes, 256 feats, 3.2M edges.
// out = stack([x0, tanh(S(x0 W0^T)), tanh(S(tanh(...) W1^T))])
// where S = segment_sum(edge_w * h[col]) by row.
//
// Inputs (metadata order):
//   d_in[0] source_feats: float32 [100000,256]
//   d_in[1] edges:        int32   [3200000,2]   (row, col)  <-- JAX x64 disabled:
//                         randint(dtype=int64) silently becomes int32!
//   d_in[2] edge_w:       float32 [3200000]
//   d_in[3] W0:           float32 [256,256]
//   d_in[4] W1:           float32 [256,256]
// d_out: float32 [3,100000,256]

#define N_NODES   100000
#define NF        256
#define FEAT_ELEMS (N_NODES * NF)

// Device scratch (allocation-free rule: __device__ globals)
__device__ float g_h[FEAT_ELEMS];     // h = x @ W^T
__device__ float g_agg[FEAT_ELEMS];   // segment sum accumulator

// ---------------------------------------------------------------------------
// Zero kernel (float4 stores)
// ---------------------------------------------------------------------------
__global__ void zero_kernel(float4* __restrict__ p, int n4) {
    int i = blockIdx.x * blockDim.x + threadIdx.x;
    if (i < n4) p[i] = make_float4(0.f, 0.f, 0.f, 0.f);
}

// ---------------------------------------------------------------------------
// SGEMM: C[M,256] = A[M,256] @ B[256,256]^T   (both row-major, K contiguous)
// 128x128 block tile, BK=8, 256 threads, 8x8 per-thread microtile.
// ---------------------------------------------------------------------------
#define BM 128
#define BN 128
#define BK 8

__global__ __launch_bounds__(256)
void gemm_nt_kernel(const float* __restrict__ A, const float* __restrict__ B,
                    float* __restrict__ C, int M) {
    __shared__ float As[BK][BM];
    __shared__ float Bs[BK][BN];

    const int tid = threadIdx.x;
    const int block_row = blockIdx.x * BM;
    const int block_col = blockIdx.y * BN;

    // Load mapping: 256 threads x 1 float4 each per tile (BM*BK = 1024 floats)
    const int ld_row = tid >> 1;          // 0..127
    const int ld_col = (tid & 1) * 4;     // 0 or 4

    const int ty = tid >> 4;              // 0..15
    const int tx = tid & 15;              // 0..15

    // Branchless guard for ragged last tile (duplicate rows computed; stores
    // are guarded).
    const int a_row = min(block_row + ld_row, M - 1);

    float acc[8][8];
#pragma unroll
    for (int i = 0; i < 8; i++)
#pragma unroll
        for (int j = 0; j < 8; j++) acc[i][j] = 0.f;

    for (int k0 = 0; k0 < NF; k0 += BK) {
        float4 av = *(const float4*)(A + (long)a_row * NF + k0 + ld_col);
        As[ld_col + 0][ld_row] = av.x;
        As[ld_col + 1][ld_row] = av.y;
        As[ld_col + 2][ld_row] = av.z;
        As[ld_col + 3][ld_row] = av.w;

        float4 bv = *(const float4*)(B + (long)(block_col + ld_row) * NF + k0 + ld_col);
        Bs[ld_col + 0][ld_row] = bv.x;
        Bs[ld_col + 1][ld_row] = bv.y;
        Bs[ld_col + 2][ld_row] = bv.z;
        Bs[ld_col + 3][ld_row] = bv.w;

        __syncthreads();

#pragma unroll
        for (int k = 0; k < BK; k++) {
            float ra[8], rb[8];
#pragma unroll
            for (int i = 0; i < 8; i++) ra[i] = As[k][ty * 8 + i];
#pragma unroll
            for (int j = 0; j < 8; j++) rb[j] = Bs[k][tx * 8 + j];
#pragma unroll
            for (int i = 0; i < 8; i++)
#pragma unroll
                for (int j = 0; j < 8; j++) acc[i][j] += ra[i] * rb[j];
        }
        __syncthreads();
    }

#pragma unroll
    for (int i = 0; i < 8; i++) {
        int r = block_row + ty * 8 + i;
        if (r < M) {
            float* crow = C + (long)r * NF + block_col + tx * 8;
            float4 v0 = make_float4(acc[i][0], acc[i][1], acc[i][2], acc[i][3]);
            float4 v1 = make_float4(acc[i][4], acc[i][5], acc[i][6], acc[i][7]);
            *(float4*)(crow + 0) = v0;
            *(float4*)(crow + 4) = v1;
        }
    }
}

// ---------------------------------------------------------------------------
// Scatter: agg[row] += w * h[col].
// One warp per edge: each of 32 lanes handles 2 float4 chunks (256 floats/edge).
// Edge pair loaded as one int2 (8B, warp-broadcast from one sector).
// red.global.add.v4.f32 (sm_90+): 4x fewer L2 reduction ops; 2 independent
// REDs per thread for MLP against the ~318-cycle L2-atomic latency.
// ---------------------------------------------------------------------------
__global__ __launch_bounds__(256)
void scatter_kernel(const float* __restrict__ h,
                    const int2* __restrict__ edges,
                    const float* __restrict__ edge_w,
                    float* __restrict__ agg, int n_edges) {
    long long gid = (long long)blockIdx.x * blockDim.x + threadIdx.x;
    int edge = (int)(gid >> 5);       // warp per edge
    int lane = (int)(gid & 31);
    if (edge >= n_edges) return;

    int2 e = __ldg(edges + edge);     // e.x = row, e.y = col
    float w = __ldg(edge_w + edge);

    const float* src = h + (long)e.y * NF + lane * 8;
    float*       dst = agg + (long)e.x * NF + lane * 8;

    float4 v0 = *(const float4*)(src);
    float4 v1 = *(const float4*)(src + 4);
    v0.x *= w; v0.y *= w; v0.z *= w; v0.w *= w;
    v1.x *= w; v1.y *= w; v1.z *= w; v1.w *= w;

    asm volatile("red.global.add.v4.f32 [%0], {%1,%2,%3,%4};"
                 :: "l"(dst), "f"(v0.x), "f"(v0.y), "f"(v0.z), "f"(v0.w)
                 : "memory");
    asm volatile("red.global.add.v4.f32 [%0], {%1,%2,%3,%4};"
                 :: "l"(dst + 4), "f"(v1.x), "f"(v1.y), "f"(v1.z), "f"(v1.w)
                 : "memory");
}

// ---------------------------------------------------------------------------
// tanh: out[i] = tanhf(agg[i])
// ---------------------------------------------------------------------------
__global__ __launch_bounds__(256)
void tanh_kernel(const float4* __restrict__ agg, float4* __restrict__ out, int n4) {
    int i = blockIdx.x * blockDim.x + threadIdx.x;
    if (i < n4) {
        float4 v = agg[i];
        v.x = tanhf(v.x);
        v.y = tanhf(v.y);
        v.z = tanhf(v.z);
        v.w = tanhf(v.w);
        out[i] = v;
    }
}

// ---------------------------------------------------------------------------
// Launch
// ---------------------------------------------------------------------------
extern "C" void kernel_launch(void* const* d_in, const int* in_sizes, int n_in,
                              void* d_out, int out_size) {
    const float* x0     = (const float*)d_in[0];
    const int2*  edges  = (const int2*)d_in[1];
    const float* edge_w = (const float*)d_in[2];
    const float* W0     = (const float*)d_in[3];
    const float* W1     = (const float*)d_in[4];
    float*       out    = (float*)d_out;

    const int M = in_sizes[0] / NF;          // 100000
    const int n_edges = in_sizes[2];         // 3200000

    float* g_h_p;
    float* g_agg_p;
    cudaGetSymbolAddress((void**)&g_h_p, g_h);
    cudaGetSymbolAddress((void**)&g_agg_p, g_agg);

    const int n4 = (M * NF) / 4;
    const int zt_blocks = (n4 + 255) / 256;
    dim3 gemm_grid((M + BM - 1) / BM, NF / BN);
    const long long scat_items = (long long)n_edges * 32;
    const int scat_blocks = (int)((scat_items + 255) / 256);

    // out0 = x0
    cudaMemcpyAsync(out, x0, (size_t)M * NF * sizeof(float),
                    cudaMemcpyDeviceToDevice);

    float* out1 = out + (size_t)M * NF;
    float* out2 = out + 2 * (size_t)M * NF;

    // Layer 1: h = x0 @ W0^T ; agg = scatter ; out1 = tanh(agg)
    gemm_nt_kernel<<<gemm_grid, 256>>>(x0, W0, g_h_p, M);
    zero_kernel<<<zt_blocks, 256>>>((float4*)g_agg_p, n4);
    scatter_kernel<<<scat_blocks, 256>>>(g_h_p, edges, edge_w, g_agg_p, n_edges);
    tanh_kernel<<<zt_blocks, 256>>>((const float4*)g_agg_p, (float4*)out1, n4);

    // Layer 2: h = out1 @ W1^T ; agg = scatter ; out2 = tanh(agg)
    gemm_nt_kernel<<<gemm_grid, 256>>>(out1, W1, g_h_p, M);
    zero_kernel<<<zt_blocks, 256>>>((float4*)g_agg_p, n4);
    scatter_kernel<<<scat_blocks, 256>>>(g_h_p, edges, edge_w, g_agg_p, n_edges);
    tanh_kernel<<<zt_blocks, 256>>>((const float4*)g_agg_p, (float4*)out2, n4);
}

// round 5
// speedup vs baseline: 1.2130x; 1.2130x over previous
#include <cuda_runtime.h>
#include <cuda_bf16.h>
#include <cstdint>

// 2-layer GCN, reordered using linearity of segment-sum:
//   out1 = tanh( (S x0) W0^T ),  out2 = tanh( (S out1) W1^T )
// where (S x)[r] = sum_e row(e)==r  w_e * x[col(e)].
//
// Inputs (metadata order):
//   d_in[0] source_feats: float32 [100000,256]
//   d_in[1] edges:        int32   [3200000,2]  (row, col)
//   d_in[2] edge_w:       float32 [3200000]
//   d_in[3] W0:           float32 [256,256]
//   d_in[4] W1:           float32 [256,256]
// d_out: float32 [3,100000,256]

#define NF 256
#define N_NODES_MAX 100000
#define FEAT_ELEMS (N_NODES_MAX * NF)

__device__ float g_agg[FEAT_ELEMS];   // segment-sum accumulator

// ---------------------------------------------------------------------------
// Zero (float4)
// ---------------------------------------------------------------------------
__global__ void zero_kernel(float4* __restrict__ p, int n4) {
    int i = blockIdx.x * blockDim.x + threadIdx.x;
    if (i < n4) p[i] = make_float4(0.f, 0.f, 0.f, 0.f);
}

// ---------------------------------------------------------------------------
// Scatter: agg[row] += w * x[col]. Warp per edge, 2x red.global.add.v4.f32.
// ---------------------------------------------------------------------------
__global__ __launch_bounds__(256)
void scatter_kernel(const float* __restrict__ x,
                    const int2* __restrict__ edges,
                    const float* __restrict__ edge_w,
                    float* __restrict__ agg, int n_edges) {
    long long gid = (long long)blockIdx.x * blockDim.x + threadIdx.x;
    int edge = (int)(gid >> 5);
    int lane = (int)(gid & 31);
    if (edge >= n_edges) return;

    int2 e = __ldg(edges + edge);     // e.x = row (dst), e.y = col (src)
    float w = __ldg(edge_w + edge);

    const float* src = x   + (long)e.y * NF + lane * 8;
    float*       dst = agg + (long)e.x * NF + lane * 8;

    float4 v0 = *(const float4*)(src);
    float4 v1 = *(const float4*)(src + 4);
    v0.x *= w; v0.y *= w; v0.z *= w; v0.w *= w;
    v1.x *= w; v1.y *= w; v1.z *= w; v1.w *= w;

    asm volatile("red.global.add.v4.f32 [%0], {%1,%2,%3,%4};"
                 :: "l"(dst), "f"(v0.x), "f"(v0.y), "f"(v0.z), "f"(v0.w) : "memory");
    asm volatile("red.global.add.v4.f32 [%0], {%1,%2,%3,%4};"
                 :: "l"(dst + 4), "f"(v1.x), "f"(v1.y), "f"(v1.z), "f"(v1.w) : "memory");
}

// ---------------------------------------------------------------------------
// TF32 tensor-core GEMM + tanh epilogue:
//   C[M,256] = tanh( A[M,256] @ B[256,256]^T )
// A row-major (m,k); B row-major (n,k) == col-major (k,n): exactly mma's
// row.col operand shapes. 128x128x32 block tile, 8 warps in 2(m) x 4(n),
// warp tile 64x32, mma.m16n8k8.tf32 with fp32 accum.
// ---------------------------------------------------------------------------
#define BM 128
#define BN 128
#define BK 32
#define KPAD 36   // 36 mod 32 = 4 -> fragment LDS (4*g + q) is conflict-free

__device__ __forceinline__ uint32_t f2tf32(float f) {
    uint32_t u;
    asm("cvt.rna.tf32.f32 %0, %1;" : "=r"(u) : "f"(f));
    return u;
}

__global__ __launch_bounds__(256)
void gemm_tf32_tanh_kernel(const float* __restrict__ A,
                           const float* __restrict__ B,
                           float* __restrict__ C, int M) {
    __shared__ uint32_t As[BM][KPAD];
    __shared__ uint32_t Bs[BN][KPAD];

    const int tid = threadIdx.x;
    const int lane = tid & 31;
    const int warp = tid >> 5;
    const int g = lane >> 2;          // group id 0..7
    const int q = lane & 3;           // thread-in-group 0..3

    const int block_row = blockIdx.x * BM;
    const int block_col = blockIdx.y * BN;
    const int m_base = (warp >> 2) * 64;   // 0 or 64
    const int n_base = (warp & 3) * 32;    // 0,32,64,96

    float acc[4][4][4];                    // [mt][nt][c0..c3]
#pragma unroll
    for (int mt = 0; mt < 4; mt++)
#pragma unroll
        for (int nt = 0; nt < 4; nt++)
#pragma unroll
            for (int c = 0; c < 4; c++) acc[mt][nt][c] = 0.f;

    for (int k0 = 0; k0 < NF; k0 += BK) {
        // Load A,B tiles: 1024 float4 each, 4 per thread; convert to tf32 bits.
#pragma unroll
        for (int i = 0; i < 4; i++) {
            int f4 = tid + i * 256;        // 0..1023
            int row = f4 >> 3;             // 0..127
            int col = (f4 & 7) * 4;        // 0..28

            int ar = min(block_row + row, M - 1);   // clamp ragged tail
            float4 av = __ldg((const float4*)(A + (long)ar * NF + k0 + col));
            uint4 at = make_uint4(f2tf32(av.x), f2tf32(av.y), f2tf32(av.z), f2tf32(av.w));
            *(uint4*)&As[row][col] = at;

            float4 bv = __ldg((const float4*)(B + (long)(block_col + row) * NF + k0 + col));
            uint4 bt = make_uint4(f2tf32(bv.x), f2tf32(bv.y), f2tf32(bv.z), f2tf32(bv.w));
            *(uint4*)&Bs[row][col] = bt;
        }
        __syncthreads();

#pragma unroll
        for (int ks = 0; ks < BK / 8; ks++) {
            const int kb = ks * 8;
            uint32_t af[4][4], bf[4][2];
#pragma unroll
            for (int mt = 0; mt < 4; mt++) {
                int r0 = m_base + mt * 16 + g;
                af[mt][0] = As[r0][kb + q];
                af[mt][1] = As[r0 + 8][kb + q];
                af[mt][2] = As[r0][kb + q + 4];
                af[mt][3] = As[r0 + 8][kb + q + 4];
            }
#pragma unroll
            for (int nt = 0; nt < 4; nt++) {
                int cn = n_base + nt * 8 + g;
                bf[nt][0] = Bs[cn][kb + q];
                bf[nt][1] = Bs[cn][kb + q + 4];
            }
#pragma unroll
            for (int mt = 0; mt < 4; mt++)
#pragma unroll
                for (int nt = 0; nt < 4; nt++) {
                    asm volatile(
                        "mma.sync.aligned.m16n8k8.row.col.f32.tf32.tf32.f32 "
                        "{%0,%1,%2,%3}, {%4,%5,%6,%7}, {%8,%9}, {%0,%1,%2,%3};"
                        : "+f"(acc[mt][nt][0]), "+f"(acc[mt][nt][1]),
                          "+f"(acc[mt][nt][2]), "+f"(acc[mt][nt][3])
                        : "r"(af[mt][0]), "r"(af[mt][1]), "r"(af[mt][2]), "r"(af[mt][3]),
                          "r"(bf[nt][0]), "r"(bf[nt][1]));
                }
        }
        __syncthreads();
    }

    // Epilogue: tanh + store. c0,c1 -> (row, 2q,2q+1); c2,c3 -> (row+8, ...)
#pragma unroll
    for (int mt = 0; mt < 4; mt++) {
        int r0 = block_row + m_base + mt * 16 + g;
        int r1 = r0 + 8;
#pragma unroll
        for (int nt = 0; nt < 4; nt++) {
            int cn = block_col + n_base + nt * 8 + q * 2;
            if (r0 < M) {
                float2 v = make_float2(tanhf(acc[mt][nt][0]), tanhf(acc[mt][nt][1]));
                *(float2*)(C + (long)r0 * NF + cn) = v;
            }
            if (r1 < M) {
                float2 v = make_float2(tanhf(acc[mt][nt][2]), tanhf(acc[mt][nt][3]));
                *(float2*)(C + (long)r1 * NF + cn) = v;
            }
        }
    }
}

// ---------------------------------------------------------------------------
// Launch
// ---------------------------------------------------------------------------
extern "C" void kernel_launch(void* const* d_in, const int* in_sizes, int n_in,
                              void* d_out, int out_size) {
    const float* x0     = (const float*)d_in[0];
    const int2*  edges  = (const int2*)d_in[1];
    const float* edge_w = (const float*)d_in[2];
    const float* W0     = (const float*)d_in[3];
    const float* W1     = (const float*)d_in[4];
    float*       out    = (float*)d_out;

    const int M = in_sizes[0] / NF;          // 100000
    const int n_edges = in_sizes[2];         // 3200000

    float* g_agg_p;
    cudaGetSymbolAddress((void**)&g_agg_p, g_agg);

    const int n4 = (M * NF) / 4;
    const int zt_blocks = (n4 + 255) / 256;
    dim3 gemm_grid((M + BM - 1) / BM, NF / BN);
    const long long scat_items = (long long)n_edges * 32;
    const int scat_blocks = (int)((scat_items + 255) / 256);

    float* out1 = out + (size_t)M * NF;
    float* out2 = out + 2 * (size_t)M * NF;

    // Layer 1 zero first, then out0 copy (copy off the critical path).
    zero_kernel<<<zt_blocks, 256>>>((float4*)g_agg_p, n4);
    cudaMemcpyAsync(out, x0, (size_t)M * NF * sizeof(float),
                    cudaMemcpyDeviceToDevice);

    // Layer 1: agg = S x0 ; out1 = tanh(agg @ W0^T)
    scatter_kernel<<<scat_blocks, 256>>>(x0, edges, edge_w, g_agg_p, n_edges);
    gemm_tf32_tanh_kernel<<<gemm_grid, 256>>>(g_agg_p, W0, out1, M);

    // Layer 2: agg = S out1 ; out2 = tanh(agg @ W1^T)
    zero_kernel<<<zt_blocks, 256>>>((float4*)g_agg_p, n4);
    scatter_kernel<<<scat_blocks, 256>>>(out1, edges, edge_w, g_agg_p, n_edges);
    gemm_tf32_tanh_kernel<<<gemm_grid, 256>>>(g_agg_p, W1, out2, M);
}